// round 14
// baseline (speedup 1.0000x reference)
#include <cuda_runtime.h>
#include <cuda_bf16.h>
#include <cstdint>

#define NN 50000
#define NE 800000
#define NG 64
#define HID 256

// ---------------- scratch (static device globals; no allocation) ----------------
__device__ float g_h1[(size_t)NN * HID];            // layer-3 fp32 output (for pool)
__device__ __nv_bfloat16 g_a1h[(size_t)NN * HID];   // gather output hi
__device__ __nv_bfloat16 g_a1l[(size_t)NN * HID];   // gather output lo
__device__ __nv_bfloat16 g_a2h[(size_t)NN * HID];   // root-feature hi (ping)
__device__ __nv_bfloat16 g_a2l[(size_t)NN * HID];
__device__ __nv_bfloat16 g_b2h[(size_t)NN * HID];   // root-feature hi (pong)
__device__ __nv_bfloat16 g_b2l[(size_t)NN * HID];
__device__ __nv_bfloat16 g_wh[393216];              // all 6 weight mats, hi
__device__ __nv_bfloat16 g_wl[393216];              // all 6 weight mats, lo
__device__ float g_inv[NN];
__device__ int   g_deg[NN];
__device__ int   g_rowptr[NN + 1];
__device__ int   g_cursor[NN];
__device__ int   g_col[NE];
__device__ int   g_src[NE];
__device__ int   g_dst[NE];
__device__ int   g_batch[NN];
__device__ int   g_bsum[64];
__device__ int   g_boff[64];
__device__ float g_pool[NG * HID];
__device__ int   g_cnt[NG];
__device__ int   g_e64, g_b64;

// ---------------- helpers ----------------
__device__ __forceinline__ uint32_t smem_to_u32(const void* p) {
    uint32_t a;
    asm("{ .reg .u64 t; cvta.to.shared.u64 t, %1; cvt.u32.u64 %0, t; }" : "=r"(a) : "l"(p));
    return a;
}
__device__ __forceinline__ uint32_t pack_bf2(float a, float b) {
    __nv_bfloat162 t = __floats2bfloat162_rn(a, b);
    return *(uint32_t*)&t;
}
__device__ __forceinline__ float2 bf2_to_f2(uint32_t u) {
    __nv_bfloat162 t = *(__nv_bfloat162*)&u;
    return make_float2(__bfloat162float(t.x), __bfloat162float(t.y));
}
__device__ __forceinline__ void ldsm_x4(uint32_t addr, uint32_t& r0, uint32_t& r1,
                                        uint32_t& r2, uint32_t& r3) {
    asm volatile("ldmatrix.sync.aligned.m8n8.x4.shared.b16 {%0,%1,%2,%3}, [%4];"
                 : "=r"(r0), "=r"(r1), "=r"(r2), "=r"(r3) : "r"(addr));
}
__device__ __forceinline__ void mma_bf16(float& c0, float& c1, float& c2, float& c3,
                                         uint32_t a0, uint32_t a1, uint32_t a2, uint32_t a3,
                                         uint32_t b0, uint32_t b1) {
    asm volatile(
        "mma.sync.aligned.m16n8k16.row.col.f32.bf16.bf16.f32 "
        "{%0,%1,%2,%3}, {%4,%5,%6,%7}, {%8,%9}, {%0,%1,%2,%3};"
        : "+f"(c0), "+f"(c1), "+f"(c2), "+f"(c3)
        : "r"(a0), "r"(a1), "r"(a2), "r"(a3), "r"(b0), "r"(b1));
}
__device__ __forceinline__ void cp16(uint32_t dst, const void* src) {
    asm volatile("cp.async.cg.shared.global [%0], [%1], 16;" :: "r"(dst), "l"(src) : "memory");
}

// ---------------- dtype detection (parallel; one sample per thread) ----------------
__global__ void detect_kernel(const void* edges, const void* batch) {
    __shared__ int eflag, bflag;
    int t = threadIdx.x;  // 128 threads
    if (t == 0) { eflag = 1; bflag = 1; }
    __syncthreads();
    if (t < 64) {
        // sample across first half of the edges buffer (in-bounds for both layouts)
        const unsigned long long* e = (const unsigned long long*)edges;
        if (e[(size_t)t * 6000 + 1] >> 32) atomicAnd(&eflag, 0);
    } else {
        // sample the tail half of batch: sorted ids there are ~50-63 (nonzero)
        const unsigned long long* b = (const unsigned long long*)batch;
        int i = t - 64;
        if (b[20000 + i * 70] >> 32) atomicAnd(&bflag, 0);
    }
    __syncthreads();
    if (t == 0) { g_e64 = eflag; g_b64 = bflag; }
}

__device__ __forceinline__ int clampn(int v, int hi) {
    return v < 0 ? 0 : (v >= hi ? hi - 1 : v);
}

// canonicalize edges to int32 AND count in-degrees (fused)
__global__ void conv_edges_kernel(const void* edges) {
    int e = blockIdx.x * blockDim.x + threadIdx.x;
    if (e >= NE) return;
    int s, d;
    if (g_e64) {
        s = (int)((const long long*)edges)[e];
        d = (int)((const long long*)edges)[NE + e];
    } else {
        s = ((const int*)edges)[e];
        d = ((const int*)edges)[NE + e];
    }
    s = clampn(s, NN);
    d = clampn(d, NN);
    g_src[e] = s;
    g_dst[e] = d;
    atomicAdd(&g_deg[d], 1);
}

// canonicalize batch + per-block smem histogram for graph counts
__global__ void conv_batch_kernel(const void* batch) {
    __shared__ int hist[NG];
    int t = threadIdx.x;
    if (t < NG) hist[t] = 0;
    __syncthreads();
    int n = blockIdx.x * blockDim.x + t;
    if (n < NN) {
        int b;
        if (g_b64) b = (int)((const long long*)batch)[n];
        else       b = ((const int*)batch)[n];
        b = clampn(b, NG);
        g_batch[n] = b;
        atomicAdd(&hist[b], 1);
    }
    __syncthreads();
    if (t < NG && hist[t]) atomicAdd(&g_cnt[t], hist[t]);
}

// ---------------- CSR build ----------------
__global__ void init_kernel() {
    int i = blockIdx.x * blockDim.x + threadIdx.x;
    if (i < NN) { g_deg[i] = 0; g_cursor[i] = 0; }
    if (i < NG * HID) g_pool[i] = 0.f;
    if (i < NG) g_cnt[i] = 0;
}

// phase A: per-block (1024-wide) local inclusive scan of g_deg; also fills g_inv
#define SCAN_BLOCKS ((NN + 1023) / 1024)
__global__ void scanA_kernel() {
    __shared__ int sh[1024];
    int t = threadIdx.x;
    int i = blockIdx.x * 1024 + t;
    int v = (i < NN) ? g_deg[i] : 0;
    if (i < NN) g_inv[i] = 1.0f / fmaxf((float)v, 1.0f);
    sh[t] = v;
    __syncthreads();
#pragma unroll
    for (int off = 1; off < 1024; off <<= 1) {
        int tv = (t >= off) ? sh[t - off] : 0;
        __syncthreads();
        sh[t] += tv;
        __syncthreads();
    }
    if (i < NN) g_rowptr[i + 1] = sh[t];
    if (t == 1023) g_bsum[blockIdx.x] = sh[1023];
}

// phase B: single tiny block scans the block sums -> exclusive offsets
__global__ void scanB_kernel() {
    __shared__ int sh[64];
    int t = threadIdx.x;  // 64 threads
    int v = (t < SCAN_BLOCKS) ? g_bsum[t] : 0;
    sh[t] = v;
    __syncthreads();
#pragma unroll
    for (int off = 1; off < 64; off <<= 1) {
        int tv = (t >= off) ? sh[t - off] : 0;
        __syncthreads();
        sh[t] += tv;
        __syncthreads();
    }
    if (t < SCAN_BLOCKS) g_boff[t] = sh[t] - v;
    if (t == 0) g_rowptr[0] = 0;
}

// phase C: add block offsets
__global__ void scanC_kernel() {
    int i = blockIdx.x * blockDim.x + threadIdx.x;
    if (i < NN) g_rowptr[i + 1] += g_boff[i >> 10];
}

__global__ void fill_kernel() {
    int e = blockIdx.x * blockDim.x + threadIdx.x;
    if (e < NE) {
        int dst = g_dst[e];
        int pos = atomicAdd(&g_cursor[dst], 1);
        g_col[g_rowptr[dst] + pos] = g_src[e];
    }
}

// ---------------- fp32 -> bf16 hi/lo conversion ----------------
__device__ __forceinline__ void split4_store(float4 v, __nv_bfloat16* dh,
                                             __nv_bfloat16* dl, size_t i4) {
    float hx = __bfloat162float(__float2bfloat16_rn(v.x));
    float hy = __bfloat162float(__float2bfloat16_rn(v.y));
    float hz = __bfloat162float(__float2bfloat16_rn(v.z));
    float hw = __bfloat162float(__float2bfloat16_rn(v.w));
    uint2 uh, ul;
    uh.x = pack_bf2(hx, hy);
    uh.y = pack_bf2(hz, hw);
    ul.x = pack_bf2(v.x - hx, v.y - hy);
    ul.y = pack_bf2(v.z - hz, v.w - hw);
    ((uint2*)dh)[i4] = uh;
    ((uint2*)dl)[i4] = ul;
}

__global__ void convert_kernel(const float* __restrict__ src,
                               __nv_bfloat16* __restrict__ dh,
                               __nv_bfloat16* __restrict__ dl, int n4) {
    int i = blockIdx.x * blockDim.x + threadIdx.x;
    if (i >= n4) return;
    split4_store(__ldg(&((const float4*)src)[i]), dh, dl, i);
}

// all 6 weight matrices in one launch (region dispatch)
#define WTOT4 81920  /* 327680 elements / 4 */
__global__ void convert_w_kernel(const float* __restrict__ w1l, const float* __restrict__ w1r,
                                 const float* __restrict__ w2l, const float* __restrict__ w2r,
                                 const float* __restrict__ w3l, const float* __restrict__ w3r,
                                 __nv_bfloat16* __restrict__ dh, __nv_bfloat16* __restrict__ dl) {
    int i = blockIdx.x * blockDim.x + threadIdx.x;
    if (i >= WTOT4) return;
    int e0 = i << 2;
    const float* src;
    int base;
    if (e0 < 65536) {
        if (e0 < 32768) { src = w1l; base = 0; } else { src = w1r; base = 32768; }
    } else if (e0 < 196608) {
        if (e0 < 131072) { src = w2l; base = 65536; } else { src = w2r; base = 131072; }
    } else {
        if (e0 < 262144) { src = w3l; base = 196608; } else { src = w3r; base = 262144; }
    }
    float4 v = __ldg((const float4*)(src + (e0 - base)));
    split4_store(v, dh, dl, i);
}

// ---------------- shared split/write epilogue for gathers ----------------
__device__ __forceinline__ void split_store4(float4 acc, float iv,
                                             __nv_bfloat16* oh, __nv_bfloat16* ol,
                                             size_t off) {
    acc.x *= iv; acc.y *= iv; acc.z *= iv; acc.w *= iv;
    split4_store(acc, oh, ol, off);
}

// mean aggregation from fp32 features (layer 1), 2x unrolled
template <int C4>
__global__ void gather_f32(const float4* __restrict__ in,
                           __nv_bfloat16* __restrict__ oh,
                           __nv_bfloat16* __restrict__ ol) {
    int n = blockIdx.x;
    int c = threadIdx.x;
    int s = g_rowptr[n];
    int e = g_rowptr[n + 1];
    float4 a0 = make_float4(0.f, 0.f, 0.f, 0.f);
    float4 a1 = make_float4(0.f, 0.f, 0.f, 0.f);
    int i = s;
    for (; i + 1 < e; i += 2) {
        int s0 = __ldg(&g_col[i]);
        int s1 = __ldg(&g_col[i + 1]);
        float4 v0 = __ldg(&in[(size_t)s0 * C4 + c]);
        float4 v1 = __ldg(&in[(size_t)s1 * C4 + c]);
        a0.x += v0.x; a0.y += v0.y; a0.z += v0.z; a0.w += v0.w;
        a1.x += v1.x; a1.y += v1.y; a1.z += v1.z; a1.w += v1.w;
    }
    if (i < e) {
        int s0 = __ldg(&g_col[i]);
        float4 v0 = __ldg(&in[(size_t)s0 * C4 + c]);
        a0.x += v0.x; a0.y += v0.y; a0.z += v0.z; a0.w += v0.w;
    }
    a0.x += a1.x; a0.y += a1.y; a0.z += a1.z; a0.w += a1.w;
    split_store4(a0, g_inv[n], oh, ol, (size_t)n * C4 + c);
}

// mean aggregation from bf16 hi/lo features (layers 2-3), 2x unrolled
template <int C4>
__global__ void gather_split(const uint2* __restrict__ inh, const uint2* __restrict__ inl,
                             __nv_bfloat16* __restrict__ oh,
                             __nv_bfloat16* __restrict__ ol) {
    int n = blockIdx.x;
    int c = threadIdx.x;
    int s = g_rowptr[n];
    int e = g_rowptr[n + 1];
    float4 a0 = make_float4(0.f, 0.f, 0.f, 0.f);
    float4 a1 = make_float4(0.f, 0.f, 0.f, 0.f);
    int i = s;
    for (; i + 1 < e; i += 2) {
        int s0 = __ldg(&g_col[i]);
        int s1 = __ldg(&g_col[i + 1]);
        size_t o0 = (size_t)s0 * C4 + c;
        size_t o1 = (size_t)s1 * C4 + c;
        uint2 uh0 = __ldg(&inh[o0]);
        uint2 ul0 = __ldg(&inl[o0]);
        uint2 uh1 = __ldg(&inh[o1]);
        uint2 ul1 = __ldg(&inl[o1]);
        {
            float2 h0 = bf2_to_f2(uh0.x), h1 = bf2_to_f2(uh0.y);
            float2 l0 = bf2_to_f2(ul0.x), l1 = bf2_to_f2(ul0.y);
            a0.x += h0.x + l0.x; a0.y += h0.y + l0.y;
            a0.z += h1.x + l1.x; a0.w += h1.y + l1.y;
        }
        {
            float2 h0 = bf2_to_f2(uh1.x), h1 = bf2_to_f2(uh1.y);
            float2 l0 = bf2_to_f2(ul1.x), l1 = bf2_to_f2(ul1.y);
            a1.x += h0.x + l0.x; a1.y += h0.y + l0.y;
            a1.z += h1.x + l1.x; a1.w += h1.y + l1.y;
        }
    }
    if (i < e) {
        int s0 = __ldg(&g_col[i]);
        size_t o0 = (size_t)s0 * C4 + c;
        uint2 uh0 = __ldg(&inh[o0]);
        uint2 ul0 = __ldg(&inl[o0]);
        float2 h0 = bf2_to_f2(uh0.x), h1 = bf2_to_f2(uh0.y);
        float2 l0 = bf2_to_f2(ul0.x), l1 = bf2_to_f2(ul0.y);
        a0.x += h0.x + l0.x; a0.y += h0.y + l0.y;
        a0.z += h1.x + l1.x; a0.w += h1.y + l1.y;
    }
    a0.x += a1.x; a0.y += a1.y; a0.z += a1.z; a0.w += a1.w;
    split_store4(a0, g_inv[n], oh, ol, (size_t)n * C4 + c);
}

// ---------------- HMMA dual GEMM + bias + relu (3-term bf16 split) ----------------
// 2-stage cp.async pipeline. CTA 128x128, 8 warps (2x4), warp tile 64x32.
#define GP 144
#define SO_AH 0
#define SO_AL 18432
#define SO_WH 36864
#define SO_WL 55296
#define STAGE_SZ 73728
#define GSMEM_TOTAL (2 * STAGE_SZ)

__global__ __launch_bounds__(256, 1) void gemm_hmma(
    const __nv_bfloat16* __restrict__ a1h, const __nv_bfloat16* __restrict__ a1l,
    const __nv_bfloat16* __restrict__ a2h, const __nv_bfloat16* __restrict__ a2l,
    const __nv_bfloat16* __restrict__ w1h, const __nv_bfloat16* __restrict__ w1l,
    const __nv_bfloat16* __restrict__ w2h, const __nv_bfloat16* __restrict__ w2l,
    const float* __restrict__ bias, float* __restrict__ outf,
    __nv_bfloat16* __restrict__ outh, __nv_bfloat16* __restrict__ outl,
    int M, int K, int writeF32, int writeSplit) {
    extern __shared__ __align__(128) char smem[];
    const uint32_t sb = smem_to_u32(smem);
    const int tid = threadIdx.x;
    const int lane = tid & 31;
    const int wid = tid >> 5;
    const int wm = wid >> 2;   // 0..1
    const int wn = wid & 3;    // 0..3
    const int mBase = blockIdx.y * 128;
    const int nBase = blockIdx.x * 128;

    float acc[4][4][4];
#pragma unroll
    for (int i = 0; i < 4; i++)
#pragma unroll
        for (int j = 0; j < 4; j++)
#pragma unroll
            for (int q = 0; q < 4; q++) acc[i][j][q] = 0.f;

    const uint32_t aOff = (uint32_t)((wm * 64 + (lane & 15)) * GP + (lane >> 4) * 16);
    const uint32_t bOff = (uint32_t)((wn * 32 + (lane & 7) + ((lane >> 4) & 1) * 8) * GP +
                                     ((lane >> 3) & 1) * 16);

    const int ksteps = K >> 6;
    const int niter = 2 * ksteps;
    const int ldRow = tid >> 3;        // 0..31 per chunk-of-32-rows pass
    const int ldC = tid & 7;           // granule 0..7

    auto issue = [&](int it, int s) {
        const int mat = it / ksteps;
        const int k0 = (it % ksteps) << 6;
        const __nv_bfloat16* Ah = mat ? a2h : a1h;
        const __nv_bfloat16* Al = mat ? a2l : a1l;
        const __nv_bfloat16* Wh = mat ? w2h : w1h;
        const __nv_bfloat16* Wl = mat ? w2l : w1l;
        const uint32_t sbase = sb + s * STAGE_SZ;
#pragma unroll
        for (int i = 0; i < 4; i++) {
            int row = ldRow + i * 32;
            int m = min(mBase + row, M - 1);
            size_t goA = (size_t)m * K + k0 + ldC * 8;
            size_t goW = (size_t)(nBase + row) * K + k0 + ldC * 8;
            uint32_t so = (uint32_t)(row * GP + ldC * 16);
            cp16(sbase + SO_AH + so, Ah + goA);
            cp16(sbase + SO_AL + so, Al + goA);
            cp16(sbase + SO_WH + so, Wh + goW);
            cp16(sbase + SO_WL + so, Wl + goW);
        }
        asm volatile("cp.async.commit_group;" ::: "memory");
    };

    issue(0, 0);
    for (int it = 0; it < niter; it++) {
        const int s = it & 1;
        if (it + 1 < niter) {
            issue(it + 1, s ^ 1);
            asm volatile("cp.async.wait_group 1;" ::: "memory");
        } else {
            asm volatile("cp.async.wait_group 0;" ::: "memory");
        }
        __syncthreads();

        const uint32_t sbase = sb + s * STAGE_SZ;
#pragma unroll
        for (int kk = 0; kk < 4; kk++) {
            const uint32_t ko = kk * 32;
            uint32_t bh[8], bl[8];
            ldsm_x4(sbase + SO_WH + bOff + ko, bh[0], bh[1], bh[2], bh[3]);
            ldsm_x4(sbase + SO_WH + bOff + ko + 16 * GP, bh[4], bh[5], bh[6], bh[7]);
            ldsm_x4(sbase + SO_WL + bOff + ko, bl[0], bl[1], bl[2], bl[3]);
            ldsm_x4(sbase + SO_WL + bOff + ko + 16 * GP, bl[4], bl[5], bl[6], bl[7]);
#pragma unroll
            for (int i = 0; i < 4; i++) {
                uint32_t ah0, ah1, ah2, ah3, al0, al1, al2, al3;
                ldsm_x4(sbase + SO_AH + aOff + ko + i * (16 * GP), ah0, ah1, ah2, ah3);
                ldsm_x4(sbase + SO_AL + aOff + ko + i * (16 * GP), al0, al1, al2, al3);
#pragma unroll
                for (int j = 0; j < 4; j++) {
                    mma_bf16(acc[i][j][0], acc[i][j][1], acc[i][j][2], acc[i][j][3],
                             ah0, ah1, ah2, ah3, bh[2 * j], bh[2 * j + 1]);
                    mma_bf16(acc[i][j][0], acc[i][j][1], acc[i][j][2], acc[i][j][3],
                             ah0, ah1, ah2, ah3, bl[2 * j], bl[2 * j + 1]);
                    mma_bf16(acc[i][j][0], acc[i][j][1], acc[i][j][2], acc[i][j][3],
                             al0, al1, al2, al3, bh[2 * j], bh[2 * j + 1]);
                }
            }
        }
        __syncthreads();
    }

    // epilogue: bias + relu + optional fp32 / hi-lo split outputs
    const int r0 = lane >> 2;
    const int cp = (lane & 3) * 2;
    float bv[4][2];
#pragma unroll
    for (int j = 0; j < 4; j++) {
        int n = nBase + wn * 32 + j * 8 + cp;
        bv[j][0] = __ldg(&bias[n]);
        bv[j][1] = __ldg(&bias[n + 1]);
    }
#pragma unroll
    for (int i = 0; i < 4; i++) {
#pragma unroll
        for (int half = 0; half < 2; half++) {
            int m = mBase + wm * 64 + i * 16 + r0 + half * 8;
            if (m < M) {
                float* ofp = outf + (size_t)m * HID;
                uint32_t* ohp = (uint32_t*)(outh + (size_t)m * HID);
                uint32_t* olp = (uint32_t*)(outl + (size_t)m * HID);
#pragma unroll
                for (int j = 0; j < 4; j++) {
                    int n = nBase + wn * 32 + j * 8 + cp;
                    float v0 = fmaxf(acc[i][j][half * 2 + 0] + bv[j][0], 0.f);
                    float v1 = fmaxf(acc[i][j][half * 2 + 1] + bv[j][1], 0.f);
                    if (writeF32) {
                        *(float2*)(ofp + n) = make_float2(v0, v1);
                    }
                    if (writeSplit) {
                        float h0 = __bfloat162float(__float2bfloat16_rn(v0));
                        float h1 = __bfloat162float(__float2bfloat16_rn(v1));
                        ohp[n >> 1] = pack_bf2(h0, h1);
                        olp[n >> 1] = pack_bf2(v0 - h0, v1 - h1);
                    }
                }
            }
        }
    }
}

// ---------------- pooling (segmented accumulate) ----------------
__global__ void pool_kernel(const float* __restrict__ h) {
    int c = threadIdx.x;  // channel, 0..255
    int n0 = blockIdx.x * 64;
    int n1 = min(n0 + 64, NN);
    int g = g_batch[n0];
    float acc = 0.f;
    for (int n = n0; n < n1; n++) {
        int bg = g_batch[n];
        if (bg != g) {
            atomicAdd(&g_pool[g * HID + c], acc);
            acc = 0.f;
            g = bg;
        }
        acc += __ldg(&h[(size_t)n * HID + c]);
    }
    atomicAdd(&g_pool[g * HID + c], acc);
}

// ---------------- final MLP head ----------------
__global__ void final_kernel(const float* __restrict__ W1, const float* __restrict__ b1,
                             const float* __restrict__ W2, const float* __restrict__ b2,
                             float* __restrict__ out) {
    int g = blockIdx.x;
    int j = threadIdx.x;  // 128 threads
    __shared__ float gv[128];
    float ic = 1.0f / fmaxf((float)g_cnt[g], 1.0f);
    const float* pr = g_pool + g * HID;
    const float* wr = W1 + j * HID;
    float dot = 0.f;
    for (int k = 0; k < HID; k += 4) {
        float4 p = *(const float4*)(pr + k);
        float4 w = *(const float4*)(wr + k);
        dot += p.x * w.x + p.y * w.y + p.z * w.z + p.w * w.w;
    }
    gv[j] = fmaxf(dot * ic + b1[j], 0.f);
    __syncthreads();
    if (j < 10) {
        float s = b2[j];
        const float* w2 = W2 + j * 128;
        for (int k = 0; k < 128; k++) s += gv[k] * w2[k];
        out[g * 10 + j] = s;
    }
}

// ---------------- launch ----------------
extern "C" void kernel_launch(void* const* d_in, const int* in_sizes, int n_in,
                              void* d_out, int out_size) {
    const float* x = (const float*)d_in[0];
    const void* edges = d_in[1];
    const void* batch = d_in[2];
    const float* W1l = (const float*)d_in[3];
    const float* b1 = (const float*)d_in[4];
    const float* W1r = (const float*)d_in[5];
    const float* W2l = (const float*)d_in[6];
    const float* b2 = (const float*)d_in[7];
    const float* W2r = (const float*)d_in[8];
    const float* W3l = (const float*)d_in[9];
    const float* b3 = (const float*)d_in[10];
    const float* W3r = (const float*)d_in[11];
    const float* l1W = (const float*)d_in[12];
    const float* l1b = (const float*)d_in[13];
    const float* l2W = (const float*)d_in[14];
    const float* l2b = (const float*)d_in[15];
    float* out = (float*)d_out;

    float* h1;
    __nv_bfloat16 *a1h, *a1l, *a2h, *a2l, *b2h, *b2l, *wh, *wl;
    cudaGetSymbolAddress((void**)&h1, g_h1);
    cudaGetSymbolAddress((void**)&a1h, g_a1h);
    cudaGetSymbolAddress((void**)&a1l, g_a1l);
    cudaGetSymbolAddress((void**)&a2h, g_a2h);
    cudaGetSymbolAddress((void**)&a2l, g_a2l);
    cudaGetSymbolAddress((void**)&b2h, g_b2h);
    cudaGetSymbolAddress((void**)&b2l, g_b2l);
    cudaGetSymbolAddress((void**)&wh, g_wh);
    cudaGetSymbolAddress((void**)&wl, g_wl);

    cudaFuncSetAttribute(gemm_hmma, cudaFuncAttributeMaxDynamicSharedMemorySize, GSMEM_TOTAL);

    const int T = 256;

    // detect + init must precede fused conv+count
    detect_kernel<<<1, 128>>>(edges, batch);
    {
        int nInit = NG * HID > NN ? NG * HID : NN;
        init_kernel<<<(nInit + T - 1) / T, T>>>();
    }
    conv_edges_kernel<<<(NE + T - 1) / T, T>>>(edges);
    conv_batch_kernel<<<(NN + T - 1) / T, T>>>(batch);

    // parallel 3-phase scan
    scanA_kernel<<<SCAN_BLOCKS, 1024>>>();
    scanB_kernel<<<1, 64>>>();
    scanC_kernel<<<(NN + T - 1) / T, T>>>();
    fill_kernel<<<(NE + T - 1) / T, T>>>();

    // weight hi/lo splits (offsets into g_wh/g_wl, in elements)
    const int O_W1L = 0, O_W1R = 32768, O_W2L = 65536, O_W2R = 131072,
              O_W3L = 196608, O_W3R = 262144;
    convert_w_kernel<<<(WTOT4 + T - 1) / T, T>>>(W1l, W1r, W2l, W2r, W3l, W3r, wh, wl);
    // x hi/lo (root features for layer 1)
    {
        int n4 = NN * 128 / 4;
        convert_kernel<<<(n4 + T - 1) / T, T>>>(x, a2h, a2l, n4);
    }

    dim3 ggrid(2, (NN + 127) / 128);  // N chunks x M chunks

    // layer 1 (K=128): A1 = gather(x), A2 = x(split) ; split-out -> b2 (= h1 hi/lo)
    gather_f32<32><<<NN, 32>>>((const float4*)x, a1h, a1l);
    gemm_hmma<<<ggrid, T, GSMEM_TOTAL>>>(a1h, a1l, a2h, a2l,
                                         wh + O_W1L, wl + O_W1L, wh + O_W1R, wl + O_W1R,
                                         b1, h1, b2h, b2l, NN, 128, 0, 1);

    // layer 2 (K=256): A1 = gather(h1 split), A2 = h1 ; split-out -> a2 (= h2 hi/lo)
    gather_split<64><<<NN, 64>>>((const uint2*)b2h, (const uint2*)b2l, a1h, a1l);
    gemm_hmma<<<ggrid, T, GSMEM_TOTAL>>>(a1h, a1l, b2h, b2l,
                                         wh + O_W2L, wl + O_W2L, wh + O_W2R, wl + O_W2R,
                                         b2, h1, a2h, a2l, NN, 256, 0, 1);

    // layer 3 (K=256): A1 = gather(h2 split), A2 = h2 ; fp32 out -> h1 (for pool)
    gather_split<64><<<NN, 64>>>((const uint2*)a2h, (const uint2*)a2l, a1h, a1l);
    gemm_hmma<<<ggrid, T, GSMEM_TOTAL>>>(a1h, a1l, a2h, a2l,
                                         wh + O_W3L, wl + O_W3L, wh + O_W3R, wl + O_W3R,
                                         b3, h1, b2h, b2l, NN, 256, 1, 0);

    // global mean pool + head
    pool_kernel<<<(NN + 63) / 64, T>>>(h1);
    final_kernel<<<NG, 128>>>(l1W, l1b, l2W, l2b, out);
}

// round 16
// speedup vs baseline: 1.0037x; 1.0037x over previous
#include <cuda_runtime.h>
#include <cuda_bf16.h>
#include <cstdint>

#define NN 50000
#define NE 800000
#define NG 64
#define HID 256

// ---------------- scratch (static device globals; no allocation) ----------------
__device__ float g_h1[(size_t)NN * HID];            // layer-3 fp32 output (for pool)
__device__ __nv_bfloat16 g_a1h[(size_t)NN * HID];   // gather output hi
__device__ __nv_bfloat16 g_a1l[(size_t)NN * HID];   // gather output lo
__device__ __nv_bfloat16 g_a2h[(size_t)NN * HID];   // root-feature hi (ping)
__device__ __nv_bfloat16 g_a2l[(size_t)NN * HID];
__device__ __nv_bfloat16 g_b2h[(size_t)NN * HID];   // root-feature hi (pong)
__device__ __nv_bfloat16 g_b2l[(size_t)NN * HID];
__device__ __nv_bfloat16 g_wh[393216];              // all 6 weight mats, hi
__device__ __nv_bfloat16 g_wl[393216];              // all 6 weight mats, lo
__device__ float g_inv[NN];
__device__ int   g_deg[NN];
__device__ int   g_rowptr[NN + 1];
__device__ int   g_cursor[NN];
__device__ int   g_col[NE];
__device__ int   g_src[NE];
__device__ int   g_dst[NE];
__device__ int   g_batch[NN];
__device__ int   g_bsum[64];
__device__ int   g_boff[64];
__device__ float g_pool[NG * HID];
__device__ int   g_cnt[NG];
__device__ int   g_e64, g_b64;

// ---------------- helpers ----------------
__device__ __forceinline__ uint32_t smem_to_u32(const void* p) {
    uint32_t a;
    asm("{ .reg .u64 t; cvta.to.shared.u64 t, %1; cvt.u32.u64 %0, t; }" : "=r"(a) : "l"(p));
    return a;
}
__device__ __forceinline__ uint32_t pack_bf2(float a, float b) {
    __nv_bfloat162 t = __floats2bfloat162_rn(a, b);
    return *(uint32_t*)&t;
}
__device__ __forceinline__ float2 bf2_to_f2(uint32_t u) {
    __nv_bfloat162 t = *(__nv_bfloat162*)&u;
    return make_float2(__bfloat162float(t.x), __bfloat162float(t.y));
}
__device__ __forceinline__ void ldsm_x4(uint32_t addr, uint32_t& r0, uint32_t& r1,
                                        uint32_t& r2, uint32_t& r3) {
    asm volatile("ldmatrix.sync.aligned.m8n8.x4.shared.b16 {%0,%1,%2,%3}, [%4];"
                 : "=r"(r0), "=r"(r1), "=r"(r2), "=r"(r3) : "r"(addr));
}
__device__ __forceinline__ void mma_bf16(float& c0, float& c1, float& c2, float& c3,
                                         uint32_t a0, uint32_t a1, uint32_t a2, uint32_t a3,
                                         uint32_t b0, uint32_t b1) {
    asm volatile(
        "mma.sync.aligned.m16n8k16.row.col.f32.bf16.bf16.f32 "
        "{%0,%1,%2,%3}, {%4,%5,%6,%7}, {%8,%9}, {%0,%1,%2,%3};"
        : "+f"(c0), "+f"(c1), "+f"(c2), "+f"(c3)
        : "r"(a0), "r"(a1), "r"(a2), "r"(a3), "r"(b0), "r"(b1));
}
__device__ __forceinline__ void cp16(uint32_t dst, const void* src) {
    asm volatile("cp.async.cg.shared.global [%0], [%1], 16;" :: "r"(dst), "l"(src) : "memory");
}

__device__ __forceinline__ int clampn(int v, int hi) {
    return v < 0 ? 0 : (v >= hi ? hi - 1 : v);
}

// ---------------- init + dtype detection (fused; block 0 detects) ----------------
__global__ void init_kernel(const void* edges, const void* batch) {
    int i = blockIdx.x * blockDim.x + threadIdx.x;
    if (i < NN) { g_deg[i] = 0; g_cursor[i] = 0; }
    if (i < NG * HID) g_pool[i] = 0.f;
    if (i < NG) g_cnt[i] = 0;
    if (blockIdx.x == 0) {
        __shared__ int eflag, bflag;
        int t = threadIdx.x;
        if (t == 0) { eflag = 1; bflag = 1; }
        __syncthreads();
        if (t < 64) {
            // sample across first half of the edges buffer (in-bounds for both layouts)
            const unsigned long long* e = (const unsigned long long*)edges;
            if (e[(size_t)t * 6000 + 1] >> 32) atomicAnd(&eflag, 0);
        } else if (t < 128) {
            // sample the tail half of batch: sorted ids there are ~50-63 (nonzero)
            const unsigned long long* b = (const unsigned long long*)batch;
            int q = t - 64;
            if (b[20000 + q * 70] >> 32) atomicAnd(&bflag, 0);
        }
        __syncthreads();
        if (t == 0) { g_e64 = eflag; g_b64 = bflag; }
    }
}

// ---------------- canonicalize edges + degrees + batch + graph counts (fused) ----
#define NBLK_NODES ((NN + 255) / 256)
__global__ void conv_edges_kernel(const void* edges, const void* batch) {
    __shared__ int hist[NG];
    int t = threadIdx.x;
    int e = blockIdx.x * blockDim.x + t;
    if (e < NE) {
        int s, d;
        if (g_e64) {
            s = (int)((const long long*)edges)[e];
            d = (int)((const long long*)edges)[NE + e];
        } else {
            s = ((const int*)edges)[e];
            d = ((const int*)edges)[NE + e];
        }
        s = clampn(s, NN);
        d = clampn(d, NN);
        g_src[e] = s;
        g_dst[e] = d;
        atomicAdd(&g_deg[d], 1);
    }
    if (blockIdx.x < NBLK_NODES) {
        if (t < NG) hist[t] = 0;
        __syncthreads();
        int n = blockIdx.x * blockDim.x + t;
        if (n < NN) {
            int b;
            if (g_b64) b = (int)((const long long*)batch)[n];
            else       b = ((const int*)batch)[n];
            b = clampn(b, NG);
            g_batch[n] = b;
            atomicAdd(&hist[b], 1);
        }
        __syncthreads();
        if (t < NG && hist[t]) atomicAdd(&g_cnt[t], hist[t]);
    }
}

// ---------------- CSR build: parallel 3-phase scan ----------------
#define SCAN_BLOCKS ((NN + 1023) / 1024)
__global__ void scanA_kernel() {
    __shared__ int sh[1024];
    int t = threadIdx.x;
    int i = blockIdx.x * 1024 + t;
    int v = (i < NN) ? g_deg[i] : 0;
    if (i < NN) g_inv[i] = 1.0f / fmaxf((float)v, 1.0f);
    sh[t] = v;
    __syncthreads();
#pragma unroll
    for (int off = 1; off < 1024; off <<= 1) {
        int tv = (t >= off) ? sh[t - off] : 0;
        __syncthreads();
        sh[t] += tv;
        __syncthreads();
    }
    if (i < NN) g_rowptr[i + 1] = sh[t];
    if (t == 1023) g_bsum[blockIdx.x] = sh[1023];
}

__global__ void scanB_kernel() {
    __shared__ int sh[64];
    int t = threadIdx.x;  // 64 threads
    int v = (t < SCAN_BLOCKS) ? g_bsum[t] : 0;
    sh[t] = v;
    __syncthreads();
#pragma unroll
    for (int off = 1; off < 64; off <<= 1) {
        int tv = (t >= off) ? sh[t - off] : 0;
        __syncthreads();
        sh[t] += tv;
        __syncthreads();
    }
    if (t < SCAN_BLOCKS) g_boff[t] = sh[t] - v;
    if (t == 0) g_rowptr[0] = 0;
}

__global__ void scanC_kernel() {
    int i = blockIdx.x * blockDim.x + threadIdx.x;
    if (i < NN) g_rowptr[i + 1] += g_boff[i >> 10];
}

__global__ void fill_kernel() {
    int e = blockIdx.x * blockDim.x + threadIdx.x;
    if (e < NE) {
        int dst = g_dst[e];
        int pos = atomicAdd(&g_cursor[dst], 1);
        g_col[g_rowptr[dst] + pos] = g_src[e];
    }
}

// ---------------- fp32 -> bf16 hi/lo conversion ----------------
__device__ __forceinline__ void split4_store(float4 v, __nv_bfloat16* dh,
                                             __nv_bfloat16* dl, size_t i4) {
    float hx = __bfloat162float(__float2bfloat16_rn(v.x));
    float hy = __bfloat162float(__float2bfloat16_rn(v.y));
    float hz = __bfloat162float(__float2bfloat16_rn(v.z));
    float hw = __bfloat162float(__float2bfloat16_rn(v.w));
    uint2 uh, ul;
    uh.x = pack_bf2(hx, hy);
    uh.y = pack_bf2(hz, hw);
    ul.x = pack_bf2(v.x - hx, v.y - hy);
    ul.y = pack_bf2(v.z - hz, v.w - hw);
    ((uint2*)dh)[i4] = uh;
    ((uint2*)dl)[i4] = ul;
}

__global__ void convert_kernel(const float* __restrict__ src,
                               __nv_bfloat16* __restrict__ dh,
                               __nv_bfloat16* __restrict__ dl, int n4) {
    int i = blockIdx.x * blockDim.x + threadIdx.x;
    if (i >= n4) return;
    split4_store(__ldg(&((const float4*)src)[i]), dh, dl, i);
}

// all 6 weight matrices in one launch (region dispatch)
#define WTOT4 81920  /* 327680 elements / 4 */
__global__ void convert_w_kernel(const float* __restrict__ w1l, const float* __restrict__ w1r,
                                 const float* __restrict__ w2l, const float* __restrict__ w2r,
                                 const float* __restrict__ w3l, const float* __restrict__ w3r,
                                 __nv_bfloat16* __restrict__ dh, __nv_bfloat16* __restrict__ dl) {
    int i = blockIdx.x * blockDim.x + threadIdx.x;
    if (i >= WTOT4) return;
    int e0 = i << 2;
    const float* src;
    int base;
    if (e0 < 65536) {
        if (e0 < 32768) { src = w1l; base = 0; } else { src = w1r; base = 32768; }
    } else if (e0 < 196608) {
        if (e0 < 131072) { src = w2l; base = 65536; } else { src = w2r; base = 131072; }
    } else {
        if (e0 < 262144) { src = w3l; base = 196608; } else { src = w3r; base = 262144; }
    }
    float4 v = __ldg((const float4*)(src + (e0 - base)));
    split4_store(v, dh, dl, i);
}

// ---------------- shared split/write epilogue for gathers ----------------
__device__ __forceinline__ void split_store4(float4 acc, float iv,
                                             __nv_bfloat16* oh, __nv_bfloat16* ol,
                                             size_t off) {
    acc.x *= iv; acc.y *= iv; acc.z *= iv; acc.w *= iv;
    split4_store(acc, oh, ol, off);
}

// mean aggregation from fp32 features (layer 1), 2x unrolled
template <int C4>
__global__ void gather_f32(const float4* __restrict__ in,
                           __nv_bfloat16* __restrict__ oh,
                           __nv_bfloat16* __restrict__ ol) {
    int n = blockIdx.x;
    int c = threadIdx.x;
    int s = g_rowptr[n];
    int e = g_rowptr[n + 1];
    float4 a0 = make_float4(0.f, 0.f, 0.f, 0.f);
    float4 a1 = make_float4(0.f, 0.f, 0.f, 0.f);
    int i = s;
    for (; i + 1 < e; i += 2) {
        int s0 = __ldg(&g_col[i]);
        int s1 = __ldg(&g_col[i + 1]);
        float4 v0 = __ldg(&in[(size_t)s0 * C4 + c]);
        float4 v1 = __ldg(&in[(size_t)s1 * C4 + c]);
        a0.x += v0.x; a0.y += v0.y; a0.z += v0.z; a0.w += v0.w;
        a1.x += v1.x; a1.y += v1.y; a1.z += v1.z; a1.w += v1.w;
    }
    if (i < e) {
        int s0 = __ldg(&g_col[i]);
        float4 v0 = __ldg(&in[(size_t)s0 * C4 + c]);
        a0.x += v0.x; a0.y += v0.y; a0.z += v0.z; a0.w += v0.w;
    }
    a0.x += a1.x; a0.y += a1.y; a0.z += a1.z; a0.w += a1.w;
    split_store4(a0, g_inv[n], oh, ol, (size_t)n * C4 + c);
}

// mean aggregation from bf16 hi/lo features (layers 2-3), 2x unrolled
template <int C4>
__global__ void gather_split(const uint2* __restrict__ inh, const uint2* __restrict__ inl,
                             __nv_bfloat16* __restrict__ oh,
                             __nv_bfloat16* __restrict__ ol) {
    int n = blockIdx.x;
    int c = threadIdx.x;
    int s = g_rowptr[n];
    int e = g_rowptr[n + 1];
    float4 a0 = make_float4(0.f, 0.f, 0.f, 0.f);
    float4 a1 = make_float4(0.f, 0.f, 0.f, 0.f);
    int i = s;
    for (; i + 1 < e; i += 2) {
        int s0 = __ldg(&g_col[i]);
        int s1 = __ldg(&g_col[i + 1]);
        size_t o0 = (size_t)s0 * C4 + c;
        size_t o1 = (size_t)s1 * C4 + c;
        uint2 uh0 = __ldg(&inh[o0]);
        uint2 ul0 = __ldg(&inl[o0]);
        uint2 uh1 = __ldg(&inh[o1]);
        uint2 ul1 = __ldg(&inl[o1]);
        {
            float2 h0 = bf2_to_f2(uh0.x), h1 = bf2_to_f2(uh0.y);
            float2 l0 = bf2_to_f2(ul0.x), l1 = bf2_to_f2(ul0.y);
            a0.x += h0.x + l0.x; a0.y += h0.y + l0.y;
            a0.z += h1.x + l1.x; a0.w += h1.y + l1.y;
        }
        {
            float2 h0 = bf2_to_f2(uh1.x), h1 = bf2_to_f2(uh1.y);
            float2 l0 = bf2_to_f2(ul1.x), l1 = bf2_to_f2(ul1.y);
            a1.x += h0.x + l0.x; a1.y += h0.y + l0.y;
            a1.z += h1.x + l1.x; a1.w += h1.y + l1.y;
        }
    }
    if (i < e) {
        int s0 = __ldg(&g_col[i]);
        size_t o0 = (size_t)s0 * C4 + c;
        uint2 uh0 = __ldg(&inh[o0]);
        uint2 ul0 = __ldg(&inl[o0]);
        float2 h0 = bf2_to_f2(uh0.x), h1 = bf2_to_f2(uh0.y);
        float2 l0 = bf2_to_f2(ul0.x), l1 = bf2_to_f2(ul0.y);
        a0.x += h0.x + l0.x; a0.y += h0.y + l0.y;
        a0.z += h1.x + l1.x; a0.w += h1.y + l1.y;
    }
    a0.x += a1.x; a0.y += a1.y; a0.z += a1.z; a0.w += a1.w;
    split_store4(a0, g_inv[n], oh, ol, (size_t)n * C4 + c);
}

// ---------------- HMMA dual GEMM + bias + relu (3-term bf16 split) ----------------
// 3-stage cp.async pipeline. CTA 128x128, 8 warps (2x4), warp tile 64x32.
#define GP 144
#define SO_AH 0
#define SO_AL 18432
#define SO_WH 36864
#define SO_WL 55296
#define STAGE_SZ 73728
#define NSTAGE 3
#define GSMEM_TOTAL (NSTAGE * STAGE_SZ)

__global__ __launch_bounds__(256, 1) void gemm_hmma(
    const __nv_bfloat16* __restrict__ a1h, const __nv_bfloat16* __restrict__ a1l,
    const __nv_bfloat16* __restrict__ a2h, const __nv_bfloat16* __restrict__ a2l,
    const __nv_bfloat16* __restrict__ w1h, const __nv_bfloat16* __restrict__ w1l,
    const __nv_bfloat16* __restrict__ w2h, const __nv_bfloat16* __restrict__ w2l,
    const float* __restrict__ bias, float* __restrict__ outf,
    __nv_bfloat16* __restrict__ outh, __nv_bfloat16* __restrict__ outl,
    int M, int K, int writeF32, int writeSplit) {
    extern __shared__ __align__(128) char smem[];
    const uint32_t sb = smem_to_u32(smem);
    const int tid = threadIdx.x;
    const int lane = tid & 31;
    const int wid = tid >> 5;
    const int wm = wid >> 2;   // 0..1
    const int wn = wid & 3;    // 0..3
    const int mBase = blockIdx.y * 128;
    const int nBase = blockIdx.x * 128;

    float acc[4][4][4];
#pragma unroll
    for (int i = 0; i < 4; i++)
#pragma unroll
        for (int j = 0; j < 4; j++)
#pragma unroll
            for (int q = 0; q < 4; q++) acc[i][j][q] = 0.f;

    const uint32_t aOff = (uint32_t)((wm * 64 + (lane & 15)) * GP + (lane >> 4) * 16);
    const uint32_t bOff = (uint32_t)((wn * 32 + (lane & 7) + ((lane >> 4) & 1) * 8) * GP +
                                     ((lane >> 3) & 1) * 16);

    const int ksteps = K >> 6;
    const int niter = 2 * ksteps;
    const int ldRow = tid >> 3;        // 0..31 per chunk-of-32-rows pass
    const int ldC = tid & 7;           // granule 0..7

    auto issue = [&](int it, int s) {
        const int mat = it / ksteps;
        const int k0 = (it % ksteps) << 6;
        const __nv_bfloat16* Ah = mat ? a2h : a1h;
        const __nv_bfloat16* Al = mat ? a2l : a1l;
        const __nv_bfloat16* Wh = mat ? w2h : w1h;
        const __nv_bfloat16* Wl = mat ? w2l : w1l;
        const uint32_t sbase = sb + s * STAGE_SZ;
#pragma unroll
        for (int i = 0; i < 4; i++) {
            int row = ldRow + i * 32;
            int m = min(mBase + row, M - 1);
            size_t goA = (size_t)m * K + k0 + ldC * 8;
            size_t goW = (size_t)(nBase + row) * K + k0 + ldC * 8;
            uint32_t so = (uint32_t)(row * GP + ldC * 16);
            cp16(sbase + SO_AH + so, Ah + goA);
            cp16(sbase + SO_AL + so, Al + goA);
            cp16(sbase + SO_WH + so, Wh + goW);
            cp16(sbase + SO_WL + so, Wl + goW);
        }
        asm volatile("cp.async.commit_group;" ::: "memory");
    };

    issue(0, 0);
    if (niter > 1) issue(1, 1);
    for (int it = 0; it < niter; it++) {
        const int s = it % NSTAGE;
        if (it + 2 < niter) {
            issue(it + 2, (it + 2) % NSTAGE);
            asm volatile("cp.async.wait_group 2;" ::: "memory");
        } else if (it + 1 < niter) {
            asm volatile("cp.async.wait_group 1;" ::: "memory");
        } else {
            asm volatile("cp.async.wait_group 0;" ::: "memory");
        }
        __syncthreads();

        const uint32_t sbase = sb + s * STAGE_SZ;
#pragma unroll
        for (int kk = 0; kk < 4; kk++) {
            const uint32_t ko = kk * 32;
            uint32_t bh[8], bl[8];
            ldsm_x4(sbase + SO_WH + bOff + ko, bh[0], bh[1], bh[2], bh[3]);
            ldsm_x4(sbase + SO_WH + bOff + ko + 16 * GP, bh[4], bh[5], bh[6], bh[7]);
            ldsm_x4(sbase + SO_WL + bOff + ko, bl[0], bl[1], bl[2], bl[3]);
            ldsm_x4(sbase + SO_WL + bOff + ko + 16 * GP, bl[4], bl[5], bl[6], bl[7]);
#pragma unroll
            for (int i = 0; i < 4; i++) {
                uint32_t ah0, ah1, ah2, ah3, al0, al1, al2, al3;
                ldsm_x4(sbase + SO_AH + aOff + ko + i * (16 * GP), ah0, ah1, ah2, ah3);
                ldsm_x4(sbase + SO_AL + aOff + ko + i * (16 * GP), al0, al1, al2, al3);
#pragma unroll
                for (int j = 0; j < 4; j++) {
                    mma_bf16(acc[i][j][0], acc[i][j][1], acc[i][j][2], acc[i][j][3],
                             ah0, ah1, ah2, ah3, bh[2 * j], bh[2 * j + 1]);
                    mma_bf16(acc[i][j][0], acc[i][j][1], acc[i][j][2], acc[i][j][3],
                             ah0, ah1, ah2, ah3, bl[2 * j], bl[2 * j + 1]);
                    mma_bf16(acc[i][j][0], acc[i][j][1], acc[i][j][2], acc[i][j][3],
                             al0, al1, al2, al3, bh[2 * j], bh[2 * j + 1]);
                }
            }
        }
        __syncthreads();
    }

    // epilogue: bias + relu + optional fp32 / hi-lo split outputs
    const int r0 = lane >> 2;
    const int cp = (lane & 3) * 2;
    float bv[4][2];
#pragma unroll
    for (int j = 0; j < 4; j++) {
        int n = nBase + wn * 32 + j * 8 + cp;
        bv[j][0] = __ldg(&bias[n]);
        bv[j][1] = __ldg(&bias[n + 1]);
    }
#pragma unroll
    for (int i = 0; i < 4; i++) {
#pragma unroll
        for (int half = 0; half < 2; half++) {
            int m = mBase + wm * 64 + i * 16 + r0 + half * 8;
            if (m < M) {
                float* ofp = outf + (size_t)m * HID;
                uint32_t* ohp = (uint32_t*)(outh + (size_t)m * HID);
                uint32_t* olp = (uint32_t*)(outl + (size_t)m * HID);
#pragma unroll
                for (int j = 0; j < 4; j++) {
                    int n = nBase + wn * 32 + j * 8 + cp;
                    float v0 = fmaxf(acc[i][j][half * 2 + 0] + bv[j][0], 0.f);
                    float v1 = fmaxf(acc[i][j][half * 2 + 1] + bv[j][1], 0.f);
                    if (writeF32) {
                        *(float2*)(ofp + n) = make_float2(v0, v1);
                    }
                    if (writeSplit) {
                        float h0 = __bfloat162float(__float2bfloat16_rn(v0));
                        float h1 = __bfloat162float(__float2bfloat16_rn(v1));
                        ohp[n >> 1] = pack_bf2(h0, h1);
                        olp[n >> 1] = pack_bf2(v0 - h0, v1 - h1);
                    }
                }
            }
        }
    }
}

// ---------------- pooling (segmented accumulate) ----------------
__global__ void pool_kernel(const float* __restrict__ h) {
    int c = threadIdx.x;  // channel, 0..255
    int n0 = blockIdx.x * 64;
    int n1 = min(n0 + 64, NN);
    int g = g_batch[n0];
    float acc = 0.f;
    for (int n = n0; n < n1; n++) {
        int bg = g_batch[n];
        if (bg != g) {
            atomicAdd(&g_pool[g * HID + c], acc);
            acc = 0.f;
            g = bg;
        }
        acc += __ldg(&h[(size_t)n * HID + c]);
    }
    atomicAdd(&g_pool[g * HID + c], acc);
}

// ---------------- final MLP head ----------------
__global__ void final_kernel(const float* __restrict__ W1, const float* __restrict__ b1,
                             const float* __restrict__ W2, const float* __restrict__ b2,
                             float* __restrict__ out) {
    int g = blockIdx.x;
    int j = threadIdx.x;  // 128 threads
    __shared__ float gv[128];
    float ic = 1.0f / fmaxf((float)g_cnt[g], 1.0f);
    const float* pr = g_pool + g * HID;
    const float* wr = W1 + j * HID;
    float dot = 0.f;
    for (int k = 0; k < HID; k += 4) {
        float4 p = *(const float4*)(pr + k);
        float4 w = *(const float4*)(wr + k);
        dot += p.x * w.x + p.y * w.y + p.z * w.z + p.w * w.w;
    }
    gv[j] = fmaxf(dot * ic + b1[j], 0.f);
    __syncthreads();
    if (j < 10) {
        float s = b2[j];
        const float* w2 = W2 + j * 128;
        for (int k = 0; k < 128; k++) s += gv[k] * w2[k];
        out[g * 10 + j] = s;
    }
}

// ---------------- launch ----------------
extern "C" void kernel_launch(void* const* d_in, const int* in_sizes, int n_in,
                              void* d_out, int out_size) {
    const float* x = (const float*)d_in[0];
    const void* edges = d_in[1];
    const void* batch = d_in[2];
    const float* W1l = (const float*)d_in[3];
    const float* b1 = (const float*)d_in[4];
    const float* W1r = (const float*)d_in[5];
    const float* W2l = (const float*)d_in[6];
    const float* b2 = (const float*)d_in[7];
    const float* W2r = (const float*)d_in[8];
    const float* W3l = (const float*)d_in[9];
    const float* b3 = (const float*)d_in[10];
    const float* W3r = (const float*)d_in[11];
    const float* l1W = (const float*)d_in[12];
    const float* l1b = (const float*)d_in[13];
    const float* l2W = (const float*)d_in[14];
    const float* l2b = (const float*)d_in[15];
    float* out = (float*)d_out;

    float* h1;
    __nv_bfloat16 *a1h, *a1l, *a2h, *a2l, *b2h, *b2l, *wh, *wl;
    cudaGetSymbolAddress((void**)&h1, g_h1);
    cudaGetSymbolAddress((void**)&a1h, g_a1h);
    cudaGetSymbolAddress((void**)&a1l, g_a1l);
    cudaGetSymbolAddress((void**)&a2h, g_a2h);
    cudaGetSymbolAddress((void**)&a2l, g_a2l);
    cudaGetSymbolAddress((void**)&b2h, g_b2h);
    cudaGetSymbolAddress((void**)&b2l, g_b2l);
    cudaGetSymbolAddress((void**)&wh, g_wh);
    cudaGetSymbolAddress((void**)&wl, g_wl);

    cudaFuncSetAttribute(gemm_hmma, cudaFuncAttributeMaxDynamicSharedMemorySize, GSMEM_TOTAL);

    const int T = 256;

    // init (+detect in block 0), then fused edge/batch canonicalize + counts
    {
        int nInit = NG * HID > NN ? NG * HID : NN;
        init_kernel<<<(nInit + T - 1) / T, T>>>(edges, batch);
    }
    conv_edges_kernel<<<(NE + T - 1) / T, T>>>(edges, batch);

    // parallel 3-phase scan + CSR fill
    scanA_kernel<<<SCAN_BLOCKS, 1024>>>();
    scanB_kernel<<<1, 64>>>();
    scanC_kernel<<<(NN + T - 1) / T, T>>>();
    fill_kernel<<<(NE + T - 1) / T, T>>>();

    // weight hi/lo splits (offsets into g_wh/g_wl, in elements)
    const int O_W1L = 0, O_W1R = 32768, O_W2L = 65536, O_W2R = 131072,
              O_W3L = 196608, O_W3R = 262144;
    convert_w_kernel<<<(WTOT4 + T - 1) / T, T>>>(W1l, W1r, W2l, W2r, W3l, W3r, wh, wl);
    // x hi/lo (root features for layer 1)
    {
        int n4 = NN * 128 / 4;
        convert_kernel<<<(n4 + T - 1) / T, T>>>(x, a2h, a2l, n4);
    }

    dim3 ggrid(2, (NN + 127) / 128);  // N chunks x M chunks

    // layer 1 (K=128): A1 = gather(x), A2 = x(split) ; split-out -> b2 (= h1 hi/lo)
    gather_f32<32><<<NN, 32>>>((const float4*)x, a1h, a1l);
    gemm_hmma<<<ggrid, T, GSMEM_TOTAL>>>(a1h, a1l, a2h, a2l,
                                         wh + O_W1L, wl + O_W1L, wh + O_W1R, wl + O_W1R,
                                         b1, h1, b2h, b2l, NN, 128, 0, 1);

    // layer 2 (K=256): A1 = gather(h1 split), A2 = h1 ; split-out -> a2 (= h2 hi/lo)
    gather_split<64><<<NN, 64>>>((const uint2*)b2h, (const uint2*)b2l, a1h, a1l);
    gemm_hmma<<<ggrid, T, GSMEM_TOTAL>>>(a1h, a1l, b2h, b2l,
                                         wh + O_W2L, wl + O_W2L, wh + O_W2R, wl + O_W2R,
                                         b2, h1, a2h, a2l, NN, 256, 0, 1);

    // layer 3 (K=256): A1 = gather(h2 split), A2 = h2 ; fp32 out -> h1 (for pool)
    gather_split<64><<<NN, 64>>>((const uint2*)a2h, (const uint2*)a2l, a1h, a1l);
    gemm_hmma<<<ggrid, T, GSMEM_TOTAL>>>(a1h, a1l, a2h, a2l,
                                         wh + O_W3L, wl + O_W3L, wh + O_W3R, wl + O_W3R,
                                         b3, h1, b2h, b2l, NN, 256, 1, 0);

    // global mean pool + head
    pool_kernel<<<(NN + 63) / 64, T>>>(h1);
    final_kernel<<<NG, 128>>>(l1W, l1b, l2W, l2b, out);
}

// round 17
// speedup vs baseline: 1.5034x; 1.4978x over previous
#include <cuda_runtime.h>
#include <cuda_bf16.h>
#include <cstdint>

#define NN 50000
#define NE 800000
#define NG 64
#define HID 256

// ---------------- scratch (static device globals; no allocation) ----------------
__device__ float g_h1[(size_t)NN * HID];            // layer-3 fp32 output (for pool)
__device__ __nv_bfloat16 g_a1h[(size_t)NN * HID];   // gather output hi
__device__ __nv_bfloat16 g_a1l[(size_t)NN * HID];   // gather output lo
__device__ __nv_bfloat16 g_a2h[(size_t)NN * HID];   // root-feature hi (ping)
__device__ __nv_bfloat16 g_a2l[(size_t)NN * HID];
__device__ __nv_bfloat16 g_b2h[(size_t)NN * HID];   // root-feature hi (pong)
__device__ __nv_bfloat16 g_b2l[(size_t)NN * HID];
__device__ __nv_bfloat16 g_wh[393216];              // all 6 weight mats, hi
__device__ __nv_bfloat16 g_wl[393216];              // all 6 weight mats, lo
__device__ float g_inv[NN];
__device__ int   g_deg[NN];
__device__ int   g_rowptr[NN + 1];
__device__ int   g_cursor[NN];
__device__ int   g_col[NE];
__device__ int   g_src[NE];
__device__ int   g_dst[NE];
__device__ int   g_batch[NN];
__device__ int   g_bsum[64];
__device__ int   g_boff[64];
__device__ float g_pool[NG * HID];
__device__ int   g_cnt[NG];
__device__ int   g_e64, g_b64;

// ---------------- helpers ----------------
__device__ __forceinline__ uint32_t smem_to_u32(const void* p) {
    uint32_t a;
    asm("{ .reg .u64 t; cvta.to.shared.u64 t, %1; cvt.u32.u64 %0, t; }" : "=r"(a) : "l"(p));
    return a;
}
__device__ __forceinline__ uint32_t pack_bf2(float a, float b) {
    __nv_bfloat162 t = __floats2bfloat162_rn(a, b);
    return *(uint32_t*)&t;
}
__device__ __forceinline__ float2 bf2_to_f2(uint32_t u) {
    __nv_bfloat162 t = *(__nv_bfloat162*)&u;
    return make_float2(__bfloat162float(t.x), __bfloat162float(t.y));
}
__device__ __forceinline__ void ldsm_x4(uint32_t addr, uint32_t& r0, uint32_t& r1,
                                        uint32_t& r2, uint32_t& r3) {
    asm volatile("ldmatrix.sync.aligned.m8n8.x4.shared.b16 {%0,%1,%2,%3}, [%4];"
                 : "=r"(r0), "=r"(r1), "=r"(r2), "=r"(r3) : "r"(addr));
}
__device__ __forceinline__ void mma_bf16(float& c0, float& c1, float& c2, float& c3,
                                         uint32_t a0, uint32_t a1, uint32_t a2, uint32_t a3,
                                         uint32_t b0, uint32_t b1) {
    asm volatile(
        "mma.sync.aligned.m16n8k16.row.col.f32.bf16.bf16.f32 "
        "{%0,%1,%2,%3}, {%4,%5,%6,%7}, {%8,%9}, {%0,%1,%2,%3};"
        : "+f"(c0), "+f"(c1), "+f"(c2), "+f"(c3)
        : "r"(a0), "r"(a1), "r"(a2), "r"(a3), "r"(b0), "r"(b1));
}
__device__ __forceinline__ void cp16(uint32_t dst, const void* src) {
    asm volatile("cp.async.cg.shared.global [%0], [%1], 16;" :: "r"(dst), "l"(src) : "memory");
}

__device__ __forceinline__ int clampn(int v, int hi) {
    return v < 0 ? 0 : (v >= hi ? hi - 1 : v);
}

// ---------------- init + dtype detection (fused; block 0 detects) ----------------
__global__ void init_kernel(const void* edges, const void* batch) {
    int i = blockIdx.x * blockDim.x + threadIdx.x;
    if (i < NN) { g_deg[i] = 0; g_cursor[i] = 0; }
    if (i < NG * HID) g_pool[i] = 0.f;
    if (i < NG) g_cnt[i] = 0;
    if (blockIdx.x == 0) {
        __shared__ int eflag, bflag;
        int t = threadIdx.x;
        if (t == 0) { eflag = 1; bflag = 1; }
        __syncthreads();
        if (t < 64) {
            // sample across first half of the edges buffer (in-bounds for both layouts)
            const unsigned long long* e = (const unsigned long long*)edges;
            if (e[(size_t)t * 6000 + 1] >> 32) atomicAnd(&eflag, 0);
        } else if (t < 128) {
            // sample the tail half of batch: sorted ids there are ~50-63 (nonzero)
            const unsigned long long* b = (const unsigned long long*)batch;
            int q = t - 64;
            if (b[20000 + q * 70] >> 32) atomicAnd(&bflag, 0);
        }
        __syncthreads();
        if (t == 0) { g_e64 = eflag; g_b64 = bflag; }
    }
}

// ---------------- canonicalize edges + degrees + batch + graph counts (fused) ----
#define NBLK_NODES ((NN + 255) / 256)
__global__ void conv_edges_kernel(const void* edges, const void* batch) {
    __shared__ int hist[NG];
    int t = threadIdx.x;
    int e = blockIdx.x * blockDim.x + t;
    if (e < NE) {
        int s, d;
        if (g_e64) {
            s = (int)((const long long*)edges)[e];
            d = (int)((const long long*)edges)[NE + e];
        } else {
            s = ((const int*)edges)[e];
            d = ((const int*)edges)[NE + e];
        }
        s = clampn(s, NN);
        d = clampn(d, NN);
        g_src[e] = s;
        g_dst[e] = d;
        atomicAdd(&g_deg[d], 1);
    }
    if (blockIdx.x < NBLK_NODES) {
        if (t < NG) hist[t] = 0;
        __syncthreads();
        int n = blockIdx.x * blockDim.x + t;
        if (n < NN) {
            int b;
            if (g_b64) b = (int)((const long long*)batch)[n];
            else       b = ((const int*)batch)[n];
            b = clampn(b, NG);
            g_batch[n] = b;
            atomicAdd(&hist[b], 1);
        }
        __syncthreads();
        if (t < NG && hist[t]) atomicAdd(&g_cnt[t], hist[t]);
    }
}

// ---------------- CSR build: parallel 3-phase scan ----------------
#define SCAN_BLOCKS ((NN + 1023) / 1024)
__global__ void scanA_kernel() {
    __shared__ int sh[1024];
    int t = threadIdx.x;
    int i = blockIdx.x * 1024 + t;
    int v = (i < NN) ? g_deg[i] : 0;
    if (i < NN) g_inv[i] = 1.0f / fmaxf((float)v, 1.0f);
    sh[t] = v;
    __syncthreads();
#pragma unroll
    for (int off = 1; off < 1024; off <<= 1) {
        int tv = (t >= off) ? sh[t - off] : 0;
        __syncthreads();
        sh[t] += tv;
        __syncthreads();
    }
    if (i < NN) g_rowptr[i + 1] = sh[t];
    if (t == 1023) g_bsum[blockIdx.x] = sh[1023];
}

__global__ void scanB_kernel() {
    __shared__ int sh[64];
    int t = threadIdx.x;  // 64 threads
    int v = (t < SCAN_BLOCKS) ? g_bsum[t] : 0;
    sh[t] = v;
    __syncthreads();
#pragma unroll
    for (int off = 1; off < 64; off <<= 1) {
        int tv = (t >= off) ? sh[t - off] : 0;
        __syncthreads();
        sh[t] += tv;
        __syncthreads();
    }
    if (t < SCAN_BLOCKS) g_boff[t] = sh[t] - v;
    if (t == 0) g_rowptr[0] = 0;
}

__global__ void scanC_kernel() {
    int i = blockIdx.x * blockDim.x + threadIdx.x;
    if (i < NN) g_rowptr[i + 1] += g_boff[i >> 10];
}

__global__ void fill_kernel() {
    int e = blockIdx.x * blockDim.x + threadIdx.x;
    if (e < NE) {
        int dst = g_dst[e];
        int pos = atomicAdd(&g_cursor[dst], 1);
        g_col[g_rowptr[dst] + pos] = g_src[e];
    }
}

// ---------------- fp32 -> bf16 hi/lo split helpers ----------------
__device__ __forceinline__ void split4_store(float4 v, __nv_bfloat16* dh,
                                             __nv_bfloat16* dl, size_t i4) {
    float hx = __bfloat162float(__float2bfloat16_rn(v.x));
    float hy = __bfloat162float(__float2bfloat16_rn(v.y));
    float hz = __bfloat162float(__float2bfloat16_rn(v.z));
    float hw = __bfloat162float(__float2bfloat16_rn(v.w));
    uint2 uh, ul;
    uh.x = pack_bf2(hx, hy);
    uh.y = pack_bf2(hz, hw);
    ul.x = pack_bf2(v.x - hx, v.y - hy);
    ul.y = pack_bf2(v.z - hz, v.w - hw);
    ((uint2*)dh)[i4] = uh;
    ((uint2*)dl)[i4] = ul;
}

// all 6 weight matrices in one launch (region dispatch)
#define WTOT4 81920  /* 327680 elements / 4 */
__global__ void convert_w_kernel(const float* __restrict__ w1l, const float* __restrict__ w1r,
                                 const float* __restrict__ w2l, const float* __restrict__ w2r,
                                 const float* __restrict__ w3l, const float* __restrict__ w3r,
                                 __nv_bfloat16* __restrict__ dh, __nv_bfloat16* __restrict__ dl) {
    int i = blockIdx.x * blockDim.x + threadIdx.x;
    if (i >= WTOT4) return;
    int e0 = i << 2;
    const float* src;
    int base;
    if (e0 < 65536) {
        if (e0 < 32768) { src = w1l; base = 0; } else { src = w1r; base = 32768; }
    } else if (e0 < 196608) {
        if (e0 < 131072) { src = w2l; base = 65536; } else { src = w2r; base = 131072; }
    } else {
        if (e0 < 262144) { src = w3l; base = 196608; } else { src = w3r; base = 262144; }
    }
    float4 v = __ldg((const float4*)(src + (e0 - base)));
    split4_store(v, dh, dl, i);
}

// ---------------- shared split/write epilogue for gathers ----------------
__device__ __forceinline__ void split_store4(float4 acc, float iv,
                                             __nv_bfloat16* oh, __nv_bfloat16* ol,
                                             size_t off) {
    acc.x *= iv; acc.y *= iv; acc.z *= iv; acc.w *= iv;
    split4_store(acc, oh, ol, off);
}

// layer-1: mean aggregation from fp32 features + inline x->hi/lo conversion
template <int C4>
__global__ void gather_f32(const float4* __restrict__ in,
                           __nv_bfloat16* __restrict__ oh,
                           __nv_bfloat16* __restrict__ ol,
                           __nv_bfloat16* __restrict__ xh,
                           __nv_bfloat16* __restrict__ xl) {
    int n = blockIdx.x;
    int c = threadIdx.x;
    // fused: convert this node's own feature row to hi/lo for the GEMM root branch
    float4 xv = __ldg(&in[(size_t)n * C4 + c]);
    split4_store(xv, xh, xl, (size_t)n * C4 + c);

    int s = g_rowptr[n];
    int e = g_rowptr[n + 1];
    float4 a0 = make_float4(0.f, 0.f, 0.f, 0.f);
    float4 a1 = make_float4(0.f, 0.f, 0.f, 0.f);
    int i = s;
    for (; i + 1 < e; i += 2) {
        int s0 = __ldg(&g_col[i]);
        int s1 = __ldg(&g_col[i + 1]);
        float4 v0 = __ldg(&in[(size_t)s0 * C4 + c]);
        float4 v1 = __ldg(&in[(size_t)s1 * C4 + c]);
        a0.x += v0.x; a0.y += v0.y; a0.z += v0.z; a0.w += v0.w;
        a1.x += v1.x; a1.y += v1.y; a1.z += v1.z; a1.w += v1.w;
    }
    if (i < e) {
        int s0 = __ldg(&g_col[i]);
        float4 v0 = __ldg(&in[(size_t)s0 * C4 + c]);
        a0.x += v0.x; a0.y += v0.y; a0.z += v0.z; a0.w += v0.w;
    }
    a0.x += a1.x; a0.y += a1.y; a0.z += a1.z; a0.w += a1.w;
    split_store4(a0, g_inv[n], oh, ol, (size_t)n * C4 + c);
}

// layers 2-3: mean aggregation from bf16 hi/lo features, 4x unrolled
template <int C4>
__global__ void gather_split(const uint2* __restrict__ inh, const uint2* __restrict__ inl,
                             __nv_bfloat16* __restrict__ oh,
                             __nv_bfloat16* __restrict__ ol) {
    int n = blockIdx.x;
    int c = threadIdx.x;
    int s = g_rowptr[n];
    int e = g_rowptr[n + 1];
    float4 a0 = make_float4(0.f, 0.f, 0.f, 0.f);
    float4 a1 = make_float4(0.f, 0.f, 0.f, 0.f);
    float4 a2 = make_float4(0.f, 0.f, 0.f, 0.f);
    float4 a3 = make_float4(0.f, 0.f, 0.f, 0.f);
    int i = s;
    for (; i + 3 < e; i += 4) {
        int s0 = __ldg(&g_col[i]);
        int s1 = __ldg(&g_col[i + 1]);
        int s2 = __ldg(&g_col[i + 2]);
        int s3 = __ldg(&g_col[i + 3]);
        size_t o0 = (size_t)s0 * C4 + c;
        size_t o1 = (size_t)s1 * C4 + c;
        size_t o2 = (size_t)s2 * C4 + c;
        size_t o3 = (size_t)s3 * C4 + c;
        uint2 uh0 = __ldg(&inh[o0]);
        uint2 ul0 = __ldg(&inl[o0]);
        uint2 uh1 = __ldg(&inh[o1]);
        uint2 ul1 = __ldg(&inl[o1]);
        uint2 uh2 = __ldg(&inh[o2]);
        uint2 ul2 = __ldg(&inl[o2]);
        uint2 uh3 = __ldg(&inh[o3]);
        uint2 ul3 = __ldg(&inl[o3]);
        {
            float2 h0 = bf2_to_f2(uh0.x), h1 = bf2_to_f2(uh0.y);
            float2 l0 = bf2_to_f2(ul0.x), l1 = bf2_to_f2(ul0.y);
            a0.x += h0.x + l0.x; a0.y += h0.y + l0.y;
            a0.z += h1.x + l1.x; a0.w += h1.y + l1.y;
        }
        {
            float2 h0 = bf2_to_f2(uh1.x), h1 = bf2_to_f2(uh1.y);
            float2 l0 = bf2_to_f2(ul1.x), l1 = bf2_to_f2(ul1.y);
            a1.x += h0.x + l0.x; a1.y += h0.y + l0.y;
            a1.z += h1.x + l1.x; a1.w += h1.y + l1.y;
        }
        {
            float2 h0 = bf2_to_f2(uh2.x), h1 = bf2_to_f2(uh2.y);
            float2 l0 = bf2_to_f2(ul2.x), l1 = bf2_to_f2(ul2.y);
            a2.x += h0.x + l0.x; a2.y += h0.y + l0.y;
            a2.z += h1.x + l1.x; a2.w += h1.y + l1.y;
        }
        {
            float2 h0 = bf2_to_f2(uh3.x), h1 = bf2_to_f2(uh3.y);
            float2 l0 = bf2_to_f2(ul3.x), l1 = bf2_to_f2(ul3.y);
            a3.x += h0.x + l0.x; a3.y += h0.y + l0.y;
            a3.z += h1.x + l1.x; a3.w += h1.y + l1.y;
        }
    }
    for (; i < e; i++) {
        int s0 = __ldg(&g_col[i]);
        size_t o0 = (size_t)s0 * C4 + c;
        uint2 uh0 = __ldg(&inh[o0]);
        uint2 ul0 = __ldg(&inl[o0]);
        float2 h0 = bf2_to_f2(uh0.x), h1 = bf2_to_f2(uh0.y);
        float2 l0 = bf2_to_f2(ul0.x), l1 = bf2_to_f2(ul0.y);
        a0.x += h0.x + l0.x; a0.y += h0.y + l0.y;
        a0.z += h1.x + l1.x; a0.w += h1.y + l1.y;
    }
    a0.x += a1.x + a2.x + a3.x;
    a0.y += a1.y + a2.y + a3.y;
    a0.z += a1.z + a2.z + a3.z;
    a0.w += a1.w + a2.w + a3.w;
    split_store4(a0, g_inv[n], oh, ol, (size_t)n * C4 + c);
}

// ---------------- HMMA dual GEMM + bias + relu (3-term bf16 split) ----------------
// 3-stage cp.async pipeline. CTA 128x128, 8 warps (2x4), warp tile 64x32.
#define GP 144
#define SO_AH 0
#define SO_AL 18432
#define SO_WH 36864
#define SO_WL 55296
#define STAGE_SZ 73728
#define NSTAGE 3
#define GSMEM_TOTAL (NSTAGE * STAGE_SZ)

__global__ __launch_bounds__(256, 1) void gemm_hmma(
    const __nv_bfloat16* __restrict__ a1h, const __nv_bfloat16* __restrict__ a1l,
    const __nv_bfloat16* __restrict__ a2h, const __nv_bfloat16* __restrict__ a2l,
    const __nv_bfloat16* __restrict__ w1h, const __nv_bfloat16* __restrict__ w1l,
    const __nv_bfloat16* __restrict__ w2h, const __nv_bfloat16* __restrict__ w2l,
    const float* __restrict__ bias, float* __restrict__ outf,
    __nv_bfloat16* __restrict__ outh, __nv_bfloat16* __restrict__ outl,
    int M, int K, int writeF32, int writeSplit) {
    extern __shared__ __align__(128) char smem[];
    const uint32_t sb = smem_to_u32(smem);
    const int tid = threadIdx.x;
    const int lane = tid & 31;
    const int wid = tid >> 5;
    const int wm = wid >> 2;   // 0..1
    const int wn = wid & 3;    // 0..3
    const int mBase = blockIdx.y * 128;
    const int nBase = blockIdx.x * 128;

    float acc[4][4][4];
#pragma unroll
    for (int i = 0; i < 4; i++)
#pragma unroll
        for (int j = 0; j < 4; j++)
#pragma unroll
            for (int q = 0; q < 4; q++) acc[i][j][q] = 0.f;

    const uint32_t aOff = (uint32_t)((wm * 64 + (lane & 15)) * GP + (lane >> 4) * 16);
    const uint32_t bOff = (uint32_t)((wn * 32 + (lane & 7) + ((lane >> 4) & 1) * 8) * GP +
                                     ((lane >> 3) & 1) * 16);

    const int ksteps = K >> 6;
    const int niter = 2 * ksteps;
    const int ldRow = tid >> 3;        // 0..31 per chunk-of-32-rows pass
    const int ldC = tid & 7;           // granule 0..7

    auto issue = [&](int it, int s) {
        const int mat = it / ksteps;
        const int k0 = (it % ksteps) << 6;
        const __nv_bfloat16* Ah = mat ? a2h : a1h;
        const __nv_bfloat16* Al = mat ? a2l : a1l;
        const __nv_bfloat16* Wh = mat ? w2h : w1h;
        const __nv_bfloat16* Wl = mat ? w2l : w1l;
        const uint32_t sbase = sb + s * STAGE_SZ;
#pragma unroll
        for (int i = 0; i < 4; i++) {
            int row = ldRow + i * 32;
            int m = min(mBase + row, M - 1);
            size_t goA = (size_t)m * K + k0 + ldC * 8;
            size_t goW = (size_t)(nBase + row) * K + k0 + ldC * 8;
            uint32_t so = (uint32_t)(row * GP + ldC * 16);
            cp16(sbase + SO_AH + so, Ah + goA);
            cp16(sbase + SO_AL + so, Al + goA);
            cp16(sbase + SO_WH + so, Wh + goW);
            cp16(sbase + SO_WL + so, Wl + goW);
        }
        asm volatile("cp.async.commit_group;" ::: "memory");
    };

    issue(0, 0);
    if (niter > 1) issue(1, 1);
    for (int it = 0; it < niter; it++) {
        const int s = it % NSTAGE;
        if (it + 2 < niter) {
            issue(it + 2, (it + 2) % NSTAGE);
            asm volatile("cp.async.wait_group 2;" ::: "memory");
        } else if (it + 1 < niter) {
            asm volatile("cp.async.wait_group 1;" ::: "memory");
        } else {
            asm volatile("cp.async.wait_group 0;" ::: "memory");
        }
        __syncthreads();

        const uint32_t sbase = sb + s * STAGE_SZ;
#pragma unroll
        for (int kk = 0; kk < 4; kk++) {
            const uint32_t ko = kk * 32;
            uint32_t bh[8], bl[8];
            ldsm_x4(sbase + SO_WH + bOff + ko, bh[0], bh[1], bh[2], bh[3]);
            ldsm_x4(sbase + SO_WH + bOff + ko + 16 * GP, bh[4], bh[5], bh[6], bh[7]);
            ldsm_x4(sbase + SO_WL + bOff + ko, bl[0], bl[1], bl[2], bl[3]);
            ldsm_x4(sbase + SO_WL + bOff + ko + 16 * GP, bl[4], bl[5], bl[6], bl[7]);
#pragma unroll
            for (int i = 0; i < 4; i++) {
                uint32_t ah0, ah1, ah2, ah3, al0, al1, al2, al3;
                ldsm_x4(sbase + SO_AH + aOff + ko + i * (16 * GP), ah0, ah1, ah2, ah3);
                ldsm_x4(sbase + SO_AL + aOff + ko + i * (16 * GP), al0, al1, al2, al3);
#pragma unroll
                for (int j = 0; j < 4; j++) {
                    mma_bf16(acc[i][j][0], acc[i][j][1], acc[i][j][2], acc[i][j][3],
                             ah0, ah1, ah2, ah3, bh[2 * j], bh[2 * j + 1]);
                    mma_bf16(acc[i][j][0], acc[i][j][1], acc[i][j][2], acc[i][j][3],
                             ah0, ah1, ah2, ah3, bl[2 * j], bl[2 * j + 1]);
                    mma_bf16(acc[i][j][0], acc[i][j][1], acc[i][j][2], acc[i][j][3],
                             al0, al1, al2, al3, bh[2 * j], bh[2 * j + 1]);
                }
            }
        }
        __syncthreads();
    }

    // epilogue: bias + relu + optional fp32 / hi-lo split outputs
    const int r0 = lane >> 2;
    const int cp = (lane & 3) * 2;
    float bv[4][2];
#pragma unroll
    for (int j = 0; j < 4; j++) {
        int n = nBase + wn * 32 + j * 8 + cp;
        bv[j][0] = __ldg(&bias[n]);
        bv[j][1] = __ldg(&bias[n + 1]);
    }
#pragma unroll
    for (int i = 0; i < 4; i++) {
#pragma unroll
        for (int half = 0; half < 2; half++) {
            int m = mBase + wm * 64 + i * 16 + r0 + half * 8;
            if (m < M) {
                float* ofp = outf + (size_t)m * HID;
                uint32_t* ohp = (uint32_t*)(outh + (size_t)m * HID);
                uint32_t* olp = (uint32_t*)(outl + (size_t)m * HID);
#pragma unroll
                for (int j = 0; j < 4; j++) {
                    int n = nBase + wn * 32 + j * 8 + cp;
                    float v0 = fmaxf(acc[i][j][half * 2 + 0] + bv[j][0], 0.f);
                    float v1 = fmaxf(acc[i][j][half * 2 + 1] + bv[j][1], 0.f);
                    if (writeF32) {
                        *(float2*)(ofp + n) = make_float2(v0, v1);
                    }
                    if (writeSplit) {
                        float h0 = __bfloat162float(__float2bfloat16_rn(v0));
                        float h1 = __bfloat162float(__float2bfloat16_rn(v1));
                        ohp[n >> 1] = pack_bf2(h0, h1);
                        olp[n >> 1] = pack_bf2(v0 - h0, v1 - h1);
                    }
                }
            }
        }
    }
}

// ---------------- pooling (segmented accumulate) ----------------
__global__ void pool_kernel(const float* __restrict__ h) {
    int c = threadIdx.x;  // channel, 0..255
    int n0 = blockIdx.x * 64;
    int n1 = min(n0 + 64, NN);
    int g = g_batch[n0];
    float acc = 0.f;
    for (int n = n0; n < n1; n++) {
        int bg = g_batch[n];
        if (bg != g) {
            atomicAdd(&g_pool[g * HID + c], acc);
            acc = 0.f;
            g = bg;
        }
        acc += __ldg(&h[(size_t)n * HID + c]);
    }
    atomicAdd(&g_pool[g * HID + c], acc);
}

// ---------------- final MLP head ----------------
__global__ void final_kernel(const float* __restrict__ W1, const float* __restrict__ b1,
                             const float* __restrict__ W2, const float* __restrict__ b2,
                             float* __restrict__ out) {
    int g = blockIdx.x;
    int j = threadIdx.x;  // 128 threads
    __shared__ float gv[128];
    float ic = 1.0f / fmaxf((float)g_cnt[g], 1.0f);
    const float* pr = g_pool + g * HID;
    const float* wr = W1 + j * HID;
    float dot = 0.f;
    for (int k = 0; k < HID; k += 4) {
        float4 p = *(const float4*)(pr + k);
        float4 w = *(const float4*)(wr + k);
        dot += p.x * w.x + p.y * w.y + p.z * w.z + p.w * w.w;
    }
    gv[j] = fmaxf(dot * ic + b1[j], 0.f);
    __syncthreads();
    if (j < 10) {
        float s = b2[j];
        const float* w2 = W2 + j * 128;
        for (int k = 0; k < 128; k++) s += gv[k] * w2[k];
        out[g * 10 + j] = s;
    }
}

// ---------------- launch ----------------
extern "C" void kernel_launch(void* const* d_in, const int* in_sizes, int n_in,
                              void* d_out, int out_size) {
    const float* x = (const float*)d_in[0];
    const void* edges = d_in[1];
    const void* batch = d_in[2];
    const float* W1l = (const float*)d_in[3];
    const float* b1 = (const float*)d_in[4];
    const float* W1r = (const float*)d_in[5];
    const float* W2l = (const float*)d_in[6];
    const float* b2 = (const float*)d_in[7];
    const float* W2r = (const float*)d_in[8];
    const float* W3l = (const float*)d_in[9];
    const float* b3 = (const float*)d_in[10];
    const float* W3r = (const float*)d_in[11];
    const float* l1W = (const float*)d_in[12];
    const float* l1b = (const float*)d_in[13];
    const float* l2W = (const float*)d_in[14];
    const float* l2b = (const float*)d_in[15];
    float* out = (float*)d_out;

    float* h1;
    __nv_bfloat16 *a1h, *a1l, *a2h, *a2l, *b2h, *b2l, *wh, *wl;
    cudaGetSymbolAddress((void**)&h1, g_h1);
    cudaGetSymbolAddress((void**)&a1h, g_a1h);
    cudaGetSymbolAddress((void**)&a1l, g_a1l);
    cudaGetSymbolAddress((void**)&a2h, g_a2h);
    cudaGetSymbolAddress((void**)&a2l, g_a2l);
    cudaGetSymbolAddress((void**)&b2h, g_b2h);
    cudaGetSymbolAddress((void**)&b2l, g_b2l);
    cudaGetSymbolAddress((void**)&wh, g_wh);
    cudaGetSymbolAddress((void**)&wl, g_wl);

    cudaFuncSetAttribute(gemm_hmma, cudaFuncAttributeMaxDynamicSharedMemorySize, GSMEM_TOTAL);

    const int T = 256;

    // init (+detect in block 0), then fused edge/batch canonicalize + counts
    {
        int nInit = NG * HID > NN ? NG * HID : NN;
        init_kernel<<<(nInit + T - 1) / T, T>>>(edges, batch);
    }
    conv_edges_kernel<<<(NE + T - 1) / T, T>>>(edges, batch);

    // parallel 3-phase scan + CSR fill
    scanA_kernel<<<SCAN_BLOCKS, 1024>>>();
    scanB_kernel<<<1, 64>>>();
    scanC_kernel<<<(NN + T - 1) / T, T>>>();
    fill_kernel<<<(NE + T - 1) / T, T>>>();

    // weight hi/lo splits (offsets into g_wh/g_wl, in elements)
    const int O_W1L = 0, O_W1R = 32768, O_W2L = 65536, O_W2R = 131072,
              O_W3L = 196608, O_W3R = 262144;
    convert_w_kernel<<<(WTOT4 + T - 1) / T, T>>>(W1l, W1r, W2l, W2r, W3l, W3r, wh, wl);

    dim3 ggrid(2, (NN + 127) / 128);  // N chunks x M chunks

    // layer 1 (K=128): A1 = gather(x) [+ fused x->split], A2 = x(split)
    gather_f32<32><<<NN, 32>>>((const float4*)x, a1h, a1l, a2h, a2l);
    gemm_hmma<<<ggrid, T, GSMEM_TOTAL>>>(a1h, a1l, a2h, a2l,
                                         wh + O_W1L, wl + O_W1L, wh + O_W1R, wl + O_W1R,
                                         b1, h1, b2h, b2l, NN, 128, 0, 1);

    // layer 2 (K=256): A1 = gather(h1 split), A2 = h1 ; split-out -> a2 (= h2 hi/lo)
    gather_split<64><<<NN, 64>>>((const uint2*)b2h, (const uint2*)b2l, a1h, a1l);
    gemm_hmma<<<ggrid, T, GSMEM_TOTAL>>>(a1h, a1l, b2h, b2l,
                                         wh + O_W2L, wl + O_W2L, wh + O_W2R, wl + O_W2R,
                                         b2, h1, a2h, a2l, NN, 256, 0, 1);

    // layer 3 (K=256): A1 = gather(h2 split), A2 = h2 ; fp32 out -> h1 (for pool)
    gather_split<64><<<NN, 64>>>((const uint2*)a2h, (const uint2*)a2l, a1h, a1l);
    gemm_hmma<<<ggrid, T, GSMEM_TOTAL>>>(a1h, a1l, a2h, a2l,
                                         wh + O_W3L, wl + O_W3L, wh + O_W3R, wl + O_W3R,
                                         b3, h1, b2h, b2l, NN, 256, 1, 0);

    // global mean pool + head
    pool_kernel<<<(NN + 63) / 64, T>>>(h1);
    final_kernel<<<NG, 128>>>(l1W, l1b, l2W, l2b, out);
}